// round 2
// baseline (speedup 1.0000x reference)
#include <cuda_runtime.h>
#include <cuda_bf16.h>
#include <cstddef>

// Shapes: user [B=32, U=128, D=256] fp32, image [B=32, I=256, D=256] fp32
// out = concat(user * img_sum[b,1,:], image * user_sum[b,1,:])

#define BB 32
#define UU 128
#define II 256
#define DD 256

// Persistent scratch for the per-(b,d) column sums (64 KB total).
__device__ float g_usum[BB * DD];  // sum over u of user[b,:,d]
__device__ float g_isum[BB * DD];  // sum over i of image[b,:,d]

__device__ __forceinline__ float4 f4add(float4 a, float4 b) {
    return make_float4(a.x + b.x, a.y + b.y, a.z + b.z, a.w + b.w);
}
__device__ __forceinline__ float4 f4mul(float4 a, float4 b) {
    return make_float4(a.x * b.x, a.y * b.y, a.z * b.z, a.w * b.w);
}

// ---------------------------------------------------------------------------
// Kernel A: column sums. grid = B * (D/32) = 256 CTAs, 256 threads.
// Each CTA owns (batch b, 32-float d-chunk). TX=8 float4 lanes, TY=32 rows.
// Per-warp load = 8 lanes x 16B over 4 rows -> four full 128B lines. MLP=12.
// ---------------------------------------------------------------------------
#define A_TX 8
#define A_TY 32
#define A_DCH 32
#define A_NCH (DD / A_DCH)   // 8

__global__ __launch_bounds__(256)
void ei_sums_kernel(const float* __restrict__ user, const float* __restrict__ img)
{
    __shared__ float4 redU[A_TY][A_TX];
    __shared__ float4 redI[A_TY][A_TX];

    const int b  = blockIdx.x >> 3;            // / A_NCH
    const int d0 = (blockIdx.x & (A_NCH - 1)) * A_DCH;
    const int tx = threadIdx.x & (A_TX - 1);
    const int ty = threadIdx.x >> 3;
    const int d  = d0 + tx * 4;
    const int rs = DD / 4;

    const float4* up = reinterpret_cast<const float4*>(user + (size_t)b * UU * DD + d);
    const float4* ip = reinterpret_cast<const float4*>(img  + (size_t)b * II * DD + d);

    float4 au = make_float4(0.f, 0.f, 0.f, 0.f);
    float4 ai = make_float4(0.f, 0.f, 0.f, 0.f);

    #pragma unroll
    for (int k = 0; k < UU / A_TY; k++)        // 4 independent loads
        au = f4add(au, up[(size_t)(ty + k * A_TY) * rs]);
    #pragma unroll
    for (int k = 0; k < II / A_TY; k++)        // 8 independent loads
        ai = f4add(ai, ip[(size_t)(ty + k * A_TY) * rs]);

    redU[ty][tx] = au;
    redI[ty][tx] = ai;
    __syncthreads();

    if (ty < 8) {   // stage 1: 32 -> 8 partials
        float4 s = f4add(f4add(redU[ty][tx], redU[ty + 8][tx]),
                         f4add(redU[ty + 16][tx], redU[ty + 24][tx]));
        float4 t = f4add(f4add(redI[ty][tx], redI[ty + 8][tx]),
                         f4add(redI[ty + 16][tx], redI[ty + 24][tx]));
        redU[ty][tx] = s;
        redI[ty][tx] = t;
    }
    __syncthreads();

    if (ty == 0) {  // stage 2: 8 -> 1, write sums
        float4 s = make_float4(0.f, 0.f, 0.f, 0.f);
        float4 t = make_float4(0.f, 0.f, 0.f, 0.f);
        #pragma unroll
        for (int k = 0; k < 8; k++) {
            s = f4add(s, redU[k][tx]);
            t = f4add(t, redI[k][tx]);
        }
        reinterpret_cast<float4*>(g_usum + b * DD + d0)[tx] = s;
        reinterpret_cast<float4*>(g_isum + b * DD + d0)[tx] = t;
    }
}

// ---------------------------------------------------------------------------
// Kernel B: elementwise scale. One float4 per thread, full-chip grid.
// user part: out[i] = user[i] * isum[b,d]; img part: out = img * usum[b,d].
// ---------------------------------------------------------------------------
#define U_TOTAL4 (BB * UU * DD / 4)   // 262144
#define I_TOTAL4 (BB * II * DD / 4)   // 524288
#define B_THREADS 256
#define B_GRID ((U_TOTAL4 + I_TOTAL4) / B_THREADS)   // 3072

__global__ __launch_bounds__(B_THREADS)
void ei_scale_kernel(const float* __restrict__ user, const float* __restrict__ img,
                     float* __restrict__ out)
{
    const int i = blockIdx.x * B_THREADS + threadIdx.x;
    const float4* us4 = reinterpret_cast<const float4*>(g_usum);
    const float4* is4 = reinterpret_cast<const float4*>(g_isum);

    if (i < U_TOTAL4) {
        const int b  = i / (UU * DD / 4);       // / 8192 (const div -> mul/shift)
        const int d4 = i & (DD / 4 - 1);        // % 64
        float4 v = reinterpret_cast<const float4*>(user)[i];
        float4 s = is4[b * (DD / 4) + d4];
        reinterpret_cast<float4*>(out)[i] = f4mul(v, s);
    } else {
        const int j  = i - U_TOTAL4;
        const int b  = j / (II * DD / 4);       // / 16384
        const int d4 = j & (DD / 4 - 1);
        float4 v = reinterpret_cast<const float4*>(img)[j];
        float4 s = us4[b * (DD / 4) + d4];
        reinterpret_cast<float4*>(out)[U_TOTAL4 + j] = f4mul(v, s);
    }
}

// ---------------------------------------------------------------------------
extern "C" void kernel_launch(void* const* d_in, const int* in_sizes, int n_in,
                              void* d_out, int out_size)
{
    (void)in_sizes; (void)n_in; (void)out_size;
    const float* user = (const float*)d_in[0];
    const float* img  = (const float*)d_in[1];
    float* out = (float*)d_out;

    ei_sums_kernel<<<BB * A_NCH, 256>>>(user, img);
    ei_scale_kernel<<<B_GRID, B_THREADS>>>(user, img, out);
}

// round 3
// speedup vs baseline: 1.2294x; 1.2294x over previous
#include <cuda_runtime.h>
#include <cuda_bf16.h>
#include <cstddef>

// Shapes: user [B=32, U=128, D=256] fp32, image [B=32, I=256, D=256] fp32
// out = concat(user * img_sum[b,1,:], image * user_sum[b,1,:])

#define BB 32
#define UU 128
#define II 256
#define DD 256

#define TX 8                 // float4 lanes -> 32 floats = 128B rows
#define TY 32                // row groups
#define NTHREADS (TX * TY)   // 256
#define DCH 32               // d-chunk per CTA
#define NCH (DD / DCH)       // 8
#define GRID (BB * NCH)      // 256

__device__ __forceinline__ float4 f4add(float4 a, float4 b) {
    return make_float4(a.x + b.x, a.y + b.y, a.z + b.z, a.w + b.w);
}
__device__ __forceinline__ float4 f4mul(float4 a, float4 b) {
    return make_float4(a.x * b.x, a.y * b.y, a.z * b.z, a.w * b.w);
}

__global__ __launch_bounds__(NTHREADS)
void ExternalInteraction_65609920413984_kernel(
    const float* __restrict__ user,
    const float* __restrict__ img,
    float* __restrict__ out_user,
    float* __restrict__ out_img)
{
    __shared__ float4 red[TY][TX];
    __shared__ float4 bsum[2][TX];   // [0] = img_sum, [1] = user_sum

    const int b  = blockIdx.x >> 3;            // / NCH
    const int d0 = (blockIdx.x & (NCH - 1)) * DCH;
    const int tx = threadIdx.x & (TX - 1);
    const int ty = threadIdx.x >> 3;
    const int d  = d0 + tx * 4;
    const int rs = DD / 4;                     // row stride in float4

    const float4* up = reinterpret_cast<const float4*>(user + (size_t)b * UU * DD + d);
    const float4* ip = reinterpret_cast<const float4*>(img  + (size_t)b * II * DD + d);
    float4* ou = reinterpret_cast<float4*>(out_user + (size_t)b * UU * DD + d);
    float4* oi = reinterpret_cast<float4*>(out_img  + (size_t)b * II * DD + d);

    // ---- Phase A: load image tile into registers, reduce column sums ----
    float4 iv[II / TY];                         // 8 x float4 = 32 regs
    #pragma unroll
    for (int k = 0; k < II / TY; k++)
        iv[k] = ip[(size_t)(ty + k * TY) * rs];

    float4 ai = iv[0];
    #pragma unroll
    for (int k = 1; k < II / TY; k++)
        ai = f4add(ai, iv[k]);

    red[ty][tx] = ai;
    __syncthreads();
    if (ty < 8) {
        float4 s = f4add(f4add(red[ty][tx], red[ty + 8][tx]),
                         f4add(red[ty + 16][tx], red[ty + 24][tx]));
        red[ty][tx] = s;
    }
    __syncthreads();
    if (ty == 0) {
        float4 s = make_float4(0.f, 0.f, 0.f, 0.f);
        #pragma unroll
        for (int k = 0; k < 8; k++) s = f4add(s, red[k][tx]);
        bsum[0][tx] = s;
    }
    __syncthreads();
    const float4 is = bsum[0][tx];             // sum_i img[b,:,d..d+3]

    // ---- Phase B: stream user once: accumulate sum AND write out_user ----
    float4 au = make_float4(0.f, 0.f, 0.f, 0.f);
    #pragma unroll
    for (int k = 0; k < UU / TY; k++) {        // 4 loads
        float4 v = up[(size_t)(ty + k * TY) * rs];
        au = f4add(au, v);
        ou[(size_t)(ty + k * TY) * rs] = f4mul(v, is);
    }

    red[ty][tx] = au;
    __syncthreads();
    if (ty < 8) {
        float4 s = f4add(f4add(red[ty][tx], red[ty + 8][tx]),
                         f4add(red[ty + 16][tx], red[ty + 24][tx]));
        red[ty][tx] = s;
    }
    __syncthreads();
    if (ty == 0) {
        float4 s = make_float4(0.f, 0.f, 0.f, 0.f);
        #pragma unroll
        for (int k = 0; k < 8; k++) s = f4add(s, red[k][tx]);
        bsum[1][tx] = s;
    }
    __syncthreads();
    const float4 us = bsum[1][tx];             // sum_u user[b,:,d..d+3]

    // ---- Phase C: write out_img straight from registers ----
    #pragma unroll
    for (int k = 0; k < II / TY; k++)
        oi[(size_t)(ty + k * TY) * rs] = f4mul(iv[k], us);
}

extern "C" void kernel_launch(void* const* d_in, const int* in_sizes, int n_in,
                              void* d_out, int out_size)
{
    (void)in_sizes; (void)n_in; (void)out_size;
    const float* user = (const float*)d_in[0];
    const float* img  = (const float*)d_in[1];
    float* out_user = (float*)d_out;
    float* out_img  = (float*)d_out + (size_t)BB * UU * DD;

    ExternalInteraction_65609920413984_kernel
        <<<GRID, NTHREADS>>>(user, img, out_user, out_img);
}